// round 1
// baseline (speedup 1.0000x reference)
#include <cuda_runtime.h>
#include <cstddef>

#define N_DIM 4096
#define B_DIM 2048
#define RANK  4
#define ALPHA 0.8862269254527580f
#define INV_N (1.0f / 4096.0f)

// Global scratch: s[RANK][B] accumulators + y[B] accumulator (40 KiB + 8 KiB)
__device__ float g_s[RANK * B_DIM];
__device__ float g_y[B_DIM];

// ---------------------------------------------------------------------------
// Kernel 0: zero the accumulators
// ---------------------------------------------------------------------------
__global__ void zero_kernel() {
    int i = blockIdx.x * blockDim.x + threadIdx.x;
    if (i < RANK * B_DIM) g_s[i] = 0.0f;
    if (i < B_DIM)        g_y[i] = 0.0f;
}

// ---------------------------------------------------------------------------
// Kernel 1: reduce  s[r][b] = sum_n v[n][r] * erf(alpha*h[n][b])
//                   y[b]    = sum_n z[n]    * erf(alpha*h[n][b])
// Each thread owns 4 consecutive columns (float4 loads of h).
// Grid: (B/1024, N/ROWS). Each block covers ROWS rows x 1024 columns.
// ---------------------------------------------------------------------------
#define ROWS 32
#define RED_THREADS 256

__global__ void reduce_kernel(const float* __restrict__ h,
                              const float* __restrict__ v,
                              const float* __restrict__ z) {
    __shared__ float sv[ROWS][RANK];
    __shared__ float sz[ROWS];
    const int tid = threadIdx.x;
    const int n0  = blockIdx.y * ROWS;

    if (tid < ROWS * RANK) {
        sv[tid / RANK][tid % RANK] = v[(size_t)(n0 + tid / RANK) * RANK + (tid % RANK)];
    }
    if (tid < ROWS) sz[tid] = z[n0 + tid];
    __syncthreads();

    const int b = (blockIdx.x * RED_THREADS + tid) * 4;

    float s0[4] = {0.f, 0.f, 0.f, 0.f};
    float s1[4] = {0.f, 0.f, 0.f, 0.f};
    float s2[4] = {0.f, 0.f, 0.f, 0.f};
    float s3[4] = {0.f, 0.f, 0.f, 0.f};
    float sy[4] = {0.f, 0.f, 0.f, 0.f};

    #pragma unroll 4
    for (int r = 0; r < ROWS; r++) {
        const int n = n0 + r;
        float4 hv = *reinterpret_cast<const float4*>(h + (size_t)n * B_DIM + b);
        float p[4];
        p[0] = erff(ALPHA * hv.x);
        p[1] = erff(ALPHA * hv.y);
        p[2] = erff(ALPHA * hv.z);
        p[3] = erff(ALPHA * hv.w);
        const float v0 = sv[r][0], v1 = sv[r][1], v2 = sv[r][2], v3 = sv[r][3];
        const float zz = sz[r];
        #pragma unroll
        for (int k = 0; k < 4; k++) {
            s0[k] = fmaf(v0, p[k], s0[k]);
            s1[k] = fmaf(v1, p[k], s1[k]);
            s2[k] = fmaf(v2, p[k], s2[k]);
            s3[k] = fmaf(v3, p[k], s3[k]);
            sy[k] = fmaf(zz, p[k], sy[k]);
        }
    }

    #pragma unroll
    for (int k = 0; k < 4; k++) {
        atomicAdd(&g_s[0 * B_DIM + b + k], s0[k]);
        atomicAdd(&g_s[1 * B_DIM + b + k], s1[k]);
        atomicAdd(&g_s[2 * B_DIM + b + k], s2[k]);
        atomicAdd(&g_s[3 * B_DIM + b + k], s3[k]);
        atomicAdd(&g_y[b + k], sy[k]);
    }
}

// ---------------------------------------------------------------------------
// Kernel 2: finalize
//   h_new[n][b] = (sum_r u[n][r]*s[r][b]) / N + m[n]*x_t[b]
//   y[b]        = g_y[b] / N
// One thread per float4 of h_new. Output layout: [ y (B) | h_new (N*B) ].
// ---------------------------------------------------------------------------
#define FIN_THREADS 256

__global__ void finalize_kernel(const float* __restrict__ x_t,
                                const float* __restrict__ u,
                                const float* __restrict__ m,
                                float* __restrict__ out) {
    const int idx = blockIdx.x * FIN_THREADS + threadIdx.x;  // over N*B/4
    const int BQ  = B_DIM / 4;
    const int bq  = idx % BQ;
    const int n   = idx / BQ;

    float4 xt = reinterpret_cast<const float4*>(x_t)[bq];
    float4 uv = reinterpret_cast<const float4*>(u)[n];   // u[n][0..3]
    const float mm = m[n];

    float4 sr0 = reinterpret_cast<const float4*>(g_s + 0 * B_DIM)[bq];
    float4 sr1 = reinterpret_cast<const float4*>(g_s + 1 * B_DIM)[bq];
    float4 sr2 = reinterpret_cast<const float4*>(g_s + 2 * B_DIM)[bq];
    float4 sr3 = reinterpret_cast<const float4*>(g_s + 3 * B_DIM)[bq];

    float4 o;
    o.x = fmaf(mm, xt.x, (uv.x * sr0.x + uv.y * sr1.x + uv.z * sr2.x + uv.w * sr3.x) * INV_N);
    o.y = fmaf(mm, xt.y, (uv.x * sr0.y + uv.y * sr1.y + uv.z * sr2.y + uv.w * sr3.y) * INV_N);
    o.z = fmaf(mm, xt.z, (uv.x * sr0.z + uv.y * sr1.z + uv.z * sr2.z + uv.w * sr3.z) * INV_N);
    o.w = fmaf(mm, xt.w, (uv.x * sr0.w + uv.y * sr1.w + uv.z * sr2.w + uv.w * sr3.w) * INV_N);

    reinterpret_cast<float4*>(out + B_DIM)[idx] = o;

    if (n == 0) {  // first B/4 threads also emit y
        float4 yv = reinterpret_cast<const float4*>(g_y)[bq];
        yv.x *= INV_N; yv.y *= INV_N; yv.z *= INV_N; yv.w *= INV_N;
        reinterpret_cast<float4*>(out)[bq] = yv;
    }
}

// ---------------------------------------------------------------------------
// Launch
// Inputs (metadata order): x_t[B], h[N*B], m[N], u[N*RANK], v[N*RANK], z[N]
// Output: y[B] then h_new[N*B], float32.
// ---------------------------------------------------------------------------
extern "C" void kernel_launch(void* const* d_in, const int* in_sizes, int n_in,
                              void* d_out, int out_size) {
    const float* x_t = (const float*)d_in[0];
    const float* h   = (const float*)d_in[1];
    const float* m   = (const float*)d_in[2];
    const float* u   = (const float*)d_in[3];
    const float* v   = (const float*)d_in[4];
    const float* z   = (const float*)d_in[5];
    float* out = (float*)d_out;

    (void)in_sizes; (void)n_in; (void)out_size;

    // Kernel 0: zero accumulators (RANK*B + B = 10240 floats)
    zero_kernel<<<(RANK * B_DIM + 255) / 256, 256>>>();

    // Kernel 1: reduction. grid = (B/(256*4), N/ROWS) = (2, 128)
    dim3 rgrid(B_DIM / (RED_THREADS * 4), N_DIM / ROWS);
    reduce_kernel<<<rgrid, RED_THREADS>>>(h, v, z);

    // Kernel 2: finalize. N*B/4 threads.
    int fin_blocks = (N_DIM * B_DIM / 4) / FIN_THREADS;
    finalize_kernel<<<fin_blocks, FIN_THREADS>>>(x_t, u, m, out);
}

// round 2
// speedup vs baseline: 1.2658x; 1.2658x over previous
#include <cuda_runtime.h>
#include <cstddef>

#define N_DIM 4096
#define B_DIM 2048
#define RANK  4
#define INV_N (1.0f / 4096.0f)

// erf(alpha*x) ~= tanh( x * (1 + x^2*(C3P + C5P*x^2)) )   [alpha folded: c1'=1 exact]
#define ERF_C3P 0.0721781f
#define ERF_C5P (-0.000887f)

// Accumulator scratch: rows 0..3 = s[r][B], row 4 = y[B]
__device__ __align__(16) float g_acc[5 * B_DIM];

typedef unsigned long long u64;

__device__ __forceinline__ u64 pack2(float lo, float hi) {
    u64 r; asm("mov.b64 %0, {%1,%2};" : "=l"(r) : "f"(lo), "f"(hi)); return r;
}
__device__ __forceinline__ void unpack2(u64 v, float& lo, float& hi) {
    asm("mov.b64 {%0,%1}, %2;" : "=f"(lo), "=f"(hi) : "l"(v));
}
__device__ __forceinline__ u64 fma2(u64 a, u64 b, u64 c) {
    u64 d; asm("fma.rn.f32x2 %0, %1, %2, %3;" : "=l"(d) : "l"(a), "l"(b), "l"(c)); return d;
}
__device__ __forceinline__ u64 mul2(u64 a, u64 b) {
    u64 d; asm("mul.rn.f32x2 %0, %1, %2;" : "=l"(d) : "l"(a), "l"(b)); return d;
}
__device__ __forceinline__ float tanh_fast(float x) {
    float y; asm("tanh.approx.f32 %0, %1;" : "=f"(y) : "f"(x)); return y;
}

// packed phi for 2 lanes
__device__ __forceinline__ u64 phi2(u64 X, u64 C3, u64 C5, u64 ONE) {
    u64 S = mul2(X, X);
    u64 K = fma2(C5, S, C3);
    K = fma2(K, S, ONE);
    u64 A = mul2(K, X);
    float a0, a1; unpack2(A, a0, a1);
    return pack2(tanh_fast(a0), tanh_fast(a1));
}

// ---------------------------------------------------------------------------
// Reduce: s[j][b] = sum_n v[n][j]*phi(h[n][b]),  y[b] = sum_n z[n]*phi(h[n][b])
// grid (2, 128), 256 threads; block covers 32 rows x 1024 cols.
// ---------------------------------------------------------------------------
#define ROWS 32
#define RED_THREADS 256

__global__ void reduce_kernel(const float* __restrict__ h,
                              const float* __restrict__ v,
                              const float* __restrict__ z) {
    __shared__ u64 svz[ROWS][5];   // (v[n][0..3], z[n]) broadcast-packed
    const int tid = threadIdx.x;
    const int n0  = blockIdx.y * ROWS;

    if (tid < ROWS * 5) {
        int r = tid / 5, j = tid % 5;
        float val = (j < 4) ? v[(size_t)(n0 + r) * RANK + j] : z[n0 + r];
        svz[r][j] = pack2(val, val);
    }
    __syncthreads();

    const u64 C3  = pack2(ERF_C3P, ERF_C3P);
    const u64 C5  = pack2(ERF_C5P, ERF_C5P);
    const u64 ONE = pack2(1.0f, 1.0f);

    const int b0 = (blockIdx.x * RED_THREADS + tid) * 4;

    u64 acc0[5], acc1[5];
    #pragma unroll
    for (int j = 0; j < 5; j++) { acc0[j] = 0ull; acc1[j] = 0ull; }

    #pragma unroll
    for (int rb = 0; rb < ROWS; rb += 8) {
        float4 hv[8];
        #pragma unroll
        for (int i = 0; i < 8; i++)
            hv[i] = *reinterpret_cast<const float4*>(h + (size_t)(n0 + rb + i) * B_DIM + b0);
        #pragma unroll
        for (int i = 0; i < 8; i++) {
            const int r = rb + i;
            u64 P0 = phi2(pack2(hv[i].x, hv[i].y), C3, C5, ONE);
            u64 P1 = phi2(pack2(hv[i].z, hv[i].w), C3, C5, ONE);
            #pragma unroll
            for (int j = 0; j < 5; j++) {
                u64 w = svz[r][j];
                acc0[j] = fma2(w, P0, acc0[j]);
                acc1[j] = fma2(w, P1, acc1[j]);
            }
        }
    }

    #pragma unroll
    for (int j = 0; j < 5; j++) {
        float a0, a1, a2, a3;
        unpack2(acc0[j], a0, a1);
        unpack2(acc1[j], a2, a3);
        float* p = g_acc + j * B_DIM + b0;
        asm volatile("red.global.add.v4.f32 [%0], {%1,%2,%3,%4};"
                     :: "l"(p), "f"(a0), "f"(a1), "f"(a2), "f"(a3) : "memory");
    }
}

// ---------------------------------------------------------------------------
// Finalize: h_new[n][b] = m[n]*x_t[b] + (sum_j u[n][j]*s[j][b])/N
//           y[b] = g_acc[4][b]/N
// Block: 4 rows x 64 quads (256 cols). grid = 1024 row-groups * 8 quad-groups.
// s/x_t/y/u/m staged in SMEM -> kernel is pure-write-bound.
// ---------------------------------------------------------------------------
#define FIN_THREADS 256

__global__ void finalize_kernel(const float* __restrict__ x_t,
                                const float* __restrict__ u,
                                const float* __restrict__ m,
                                float* __restrict__ out) {
    __shared__ float4 s_s[4][64];
    __shared__ float4 s_x[64];
    __shared__ float4 s_y[64];
    __shared__ float4 s_u[4];
    __shared__ float  s_m[4];

    const int tid = threadIdx.x;
    const int qg  = blockIdx.x & 7;          // quad group (8 of 64 quads)
    const int rg  = blockIdx.x >> 3;         // row group (1024 of 4 rows)
    const int q0  = qg * 64;
    const int n0  = rg * 4;

    {
        const int j = tid >> 6, q = tid & 63;
        float4 sv = *reinterpret_cast<const float4*>(g_acc + j * B_DIM + (q0 + q) * 4);
        sv.x *= INV_N; sv.y *= INV_N; sv.z *= INV_N; sv.w *= INV_N;
        s_s[j][q] = sv;
        if (tid < 64) {
            s_x[q] = reinterpret_cast<const float4*>(x_t)[q0 + q];
        } else if (tid < 128) {
            float4 yv = *reinterpret_cast<const float4*>(g_acc + 4 * B_DIM + (q0 + q) * 4);
            yv.x *= INV_N; yv.y *= INV_N; yv.z *= INV_N; yv.w *= INV_N;
            s_y[q] = yv;
        }
        if (tid < 4) {
            s_u[tid] = reinterpret_cast<const float4*>(u)[n0 + tid];
            s_m[tid] = m[n0 + tid];
        }
    }
    __syncthreads();

    const int ty = tid >> 6;        // row within group
    const int tx = tid & 63;        // quad within group
    const int n  = n0 + ty;
    const int q  = q0 + tx;

    const float4 uv = s_u[ty];
    const float  mm = s_m[ty];
    const float4 a = s_s[0][tx], b = s_s[1][tx], c = s_s[2][tx], d = s_s[3][tx];
    const float4 xt = s_x[tx];

    float4 o;
    o.x = fmaf(mm, xt.x, uv.x * a.x + uv.y * b.x + uv.z * c.x + uv.w * d.x);
    o.y = fmaf(mm, xt.y, uv.x * a.y + uv.y * b.y + uv.z * c.y + uv.w * d.y);
    o.z = fmaf(mm, xt.z, uv.x * a.z + uv.y * b.z + uv.z * c.z + uv.w * d.z);
    o.w = fmaf(mm, xt.w, uv.x * a.w + uv.y * b.w + uv.z * c.w + uv.w * d.w);

    reinterpret_cast<float4*>(out + B_DIM)[(size_t)n * (B_DIM / 4) + q] = o;

    if (n == 0) {
        reinterpret_cast<float4*>(out)[q] = s_y[tx];
    }
}

// ---------------------------------------------------------------------------
// Launch. Inputs: x_t[B], h[N*B], m[N], u[N*4], v[N*4], z[N].
// Output: [ y (B) | h_new (N*B) ] float32.
// ---------------------------------------------------------------------------
extern "C" void kernel_launch(void* const* d_in, const int* in_sizes, int n_in,
                              void* d_out, int out_size) {
    const float* x_t = (const float*)d_in[0];
    const float* h   = (const float*)d_in[1];
    const float* m   = (const float*)d_in[2];
    const float* u   = (const float*)d_in[3];
    const float* v   = (const float*)d_in[4];
    const float* z   = (const float*)d_in[5];
    float* out = (float*)d_out;
    (void)in_sizes; (void)n_in; (void)out_size;

    void* acc_ptr = nullptr;
    cudaGetSymbolAddress(&acc_ptr, g_acc);
    cudaMemsetAsync(acc_ptr, 0, 5 * B_DIM * sizeof(float));

    dim3 rgrid(B_DIM / (RED_THREADS * 4), N_DIM / ROWS);   // (2, 128)
    reduce_kernel<<<rgrid, RED_THREADS>>>(h, v, z);

    int fin_blocks = (N_DIM / 4) * (B_DIM / 256);           // 1024 * 8 = 8192
    finalize_kernel<<<fin_blocks, FIN_THREADS>>>(x_t, u, m, out);
}

// round 3
// speedup vs baseline: 1.5368x; 1.2140x over previous
#include <cuda_runtime.h>
#include <cstddef>

#define N_DIM 4096
#define B_DIM 2048
#define RANK  4
#define INV_N (1.0f / 4096.0f)

// erf(alpha*x) ~= tanh( x * (1 + x^2*(C3P + C5P*x^2)) )   [alpha folded: c1'=1]
#define ERF_C3P 0.0721781f
#define ERF_C5P (-0.000887f)

// Accumulator scratch: rows 0..3 = s[r][B], row 4 = y_acc[B]
__device__ __align__(16) float g_acc[5 * B_DIM];

typedef unsigned long long u64;

__device__ __forceinline__ u64 pack2(float lo, float hi) {
    u64 r; asm("mov.b64 %0, {%1,%2};" : "=l"(r) : "f"(lo), "f"(hi)); return r;
}
__device__ __forceinline__ void unpack2(u64 v, float& lo, float& hi) {
    asm("mov.b64 {%0,%1}, %2;" : "=f"(lo), "=f"(hi) : "l"(v));
}
__device__ __forceinline__ u64 fma2(u64 a, u64 b, u64 c) {
    u64 d; asm("fma.rn.f32x2 %0, %1, %2, %3;" : "=l"(d) : "l"(a), "l"(b), "l"(c)); return d;
}
__device__ __forceinline__ u64 mul2(u64 a, u64 b) {
    u64 d; asm("mul.rn.f32x2 %0, %1, %2;" : "=l"(d) : "l"(a), "l"(b)); return d;
}
__device__ __forceinline__ float tanh_fast(float x) {
    float y; asm("tanh.approx.f32 %0, %1;" : "=f"(y) : "f"(x)); return y;
}

__device__ __forceinline__ u64 phi2(u64 X, u64 C3, u64 C5, u64 ONE) {
    u64 S = mul2(X, X);
    u64 K = fma2(C5, S, C3);
    K = fma2(K, S, ONE);
    u64 A = mul2(K, X);
    float a0, a1; unpack2(A, a0, a1);
    return pack2(tanh_fast(a0), tanh_fast(a1));
}

// ---------------------------------------------------------------------------
// Reduce: s[j][b] = sum_n v[n][j]*phi(h[n][b]),  y[b] = sum_n z[n]*phi(h[n][b])
// grid (2, 256), 256 threads; block covers 16 rows x 1024 cols.
// ---------------------------------------------------------------------------
#define ROWS 16
#define RED_THREADS 256

__global__ void reduce_kernel(const float* __restrict__ h,
                              const float* __restrict__ v,
                              const float* __restrict__ z) {
    __shared__ u64 svz[ROWS][5];   // (v[n][0..3], z[n]) broadcast-packed
    const int tid = threadIdx.x;
    const int n0  = blockIdx.y * ROWS;

    if (tid < ROWS * 5) {
        int r = tid / 5, j = tid % 5;
        float val = (j < 4) ? v[(size_t)(n0 + r) * RANK + j] : z[n0 + r];
        svz[r][j] = pack2(val, val);
    }
    __syncthreads();

    const u64 C3  = pack2(ERF_C3P, ERF_C3P);
    const u64 C5  = pack2(ERF_C5P, ERF_C5P);
    const u64 ONE = pack2(1.0f, 1.0f);

    const int b0 = (blockIdx.x * RED_THREADS + tid) * 4;

    u64 acc0[5], acc1[5];
    #pragma unroll
    for (int j = 0; j < 5; j++) { acc0[j] = 0ull; acc1[j] = 0ull; }

    #pragma unroll
    for (int rb = 0; rb < ROWS; rb += 8) {
        float4 hv[8];
        #pragma unroll
        for (int i = 0; i < 8; i++)
            hv[i] = *reinterpret_cast<const float4*>(h + (size_t)(n0 + rb + i) * B_DIM + b0);
        #pragma unroll
        for (int i = 0; i < 8; i++) {
            const int r = rb + i;
            u64 P0 = phi2(pack2(hv[i].x, hv[i].y), C3, C5, ONE);
            u64 P1 = phi2(pack2(hv[i].z, hv[i].w), C3, C5, ONE);
            #pragma unroll
            for (int j = 0; j < 5; j++) {
                u64 w = svz[r][j];
                acc0[j] = fma2(w, P0, acc0[j]);
                acc1[j] = fma2(w, P1, acc1[j]);
            }
        }
    }

    #pragma unroll
    for (int j = 0; j < 5; j++) {
        float a0, a1, a2, a3;
        unpack2(acc0[j], a0, a1);
        unpack2(acc1[j], a2, a3);
        float* p = g_acc + j * B_DIM + b0;
        asm volatile("red.global.add.v4.f32 [%0], {%1,%2,%3,%4};"
                     :: "l"(p), "f"(a0), "f"(a1), "f"(a2), "f"(a3) : "memory");
    }
}

// ---------------------------------------------------------------------------
// Finalize: h_new[n][b] = m[n]*x_t[b] + (sum_j u[n][j]*s[j][b])/N
//           y[b] = g_acc[4][b]/N
// Thread owns a fixed column-quad q; s[0..3][q], x_t[q] live in registers;
// loop over NR=32 rows: 1 broadcast LDS of (u[n],m[n]) + 16 FMA + 1 STG.128.
// grid = 2 (b halves) * 128 (row groups) = 256 blocks of 256 threads.
// ---------------------------------------------------------------------------
#define NR 32
#define FIN_THREADS 256

__global__ void finalize_kernel(const float* __restrict__ x_t,
                                const float* __restrict__ u,
                                const float* __restrict__ m,
                                float* __restrict__ out) {
    __shared__ float4 s_u[NR];
    __shared__ float  s_m[NR];

    const int tid = threadIdx.x;
    const int qb  = blockIdx.x & 1;          // which half of the 512 quads
    const int rg  = blockIdx.x >> 1;         // row group, NR rows each
    const int n0  = rg * NR;
    const int q   = qb * FIN_THREADS + tid;  // column quad index [0,512)

    if (tid < NR) {
        s_u[tid] = reinterpret_cast<const float4*>(u)[n0 + tid];
        s_m[tid] = m[n0 + tid];
    }

    // Hoist s-rows and x_t for this quad into registers (scaled by 1/N)
    const int BQ = B_DIM / 4;
    float4 a = reinterpret_cast<const float4*>(g_acc)[0 * BQ + q];
    float4 b = reinterpret_cast<const float4*>(g_acc)[1 * BQ + q];
    float4 c = reinterpret_cast<const float4*>(g_acc)[2 * BQ + q];
    float4 d = reinterpret_cast<const float4*>(g_acc)[3 * BQ + q];
    a.x *= INV_N; a.y *= INV_N; a.z *= INV_N; a.w *= INV_N;
    b.x *= INV_N; b.y *= INV_N; b.z *= INV_N; b.w *= INV_N;
    c.x *= INV_N; c.y *= INV_N; c.z *= INV_N; c.w *= INV_N;
    d.x *= INV_N; d.y *= INV_N; d.z *= INV_N; d.w *= INV_N;
    const float4 xt = reinterpret_cast<const float4*>(x_t)[q];

    __syncthreads();

    float4* op = reinterpret_cast<float4*>(out + B_DIM) + (size_t)n0 * BQ + q;

    #pragma unroll 8
    for (int r = 0; r < NR; r++) {
        const float4 uv = s_u[r];
        const float  mm = s_m[r];
        float4 o;
        o.x = fmaf(uv.x, a.x, fmaf(uv.y, b.x, fmaf(uv.z, c.x, fmaf(uv.w, d.x, mm * xt.x))));
        o.y = fmaf(uv.x, a.y, fmaf(uv.y, b.y, fmaf(uv.z, c.y, fmaf(uv.w, d.y, mm * xt.y))));
        o.z = fmaf(uv.x, a.z, fmaf(uv.y, b.z, fmaf(uv.z, c.z, fmaf(uv.w, d.z, mm * xt.z))));
        o.w = fmaf(uv.x, a.w, fmaf(uv.y, b.w, fmaf(uv.z, c.w, fmaf(uv.w, d.w, mm * xt.w))));
        *op = o;
        op += BQ;
    }

    if (rg == 0) {  // blocks 0 and 1 also emit y = y_acc / N
        float4 yv = reinterpret_cast<const float4*>(g_acc)[4 * BQ + q];
        yv.x *= INV_N; yv.y *= INV_N; yv.z *= INV_N; yv.w *= INV_N;
        reinterpret_cast<float4*>(out)[q] = yv;
    }
}

// ---------------------------------------------------------------------------
// Launch. Inputs: x_t[B], h[N*B], m[N], u[N*4], v[N*4], z[N].
// Output: [ y (B) | h_new (N*B) ] float32.
// ---------------------------------------------------------------------------
extern "C" void kernel_launch(void* const* d_in, const int* in_sizes, int n_in,
                              void* d_out, int out_size) {
    const float* x_t = (const float*)d_in[0];
    const float* h   = (const float*)d_in[1];
    const float* m   = (const float*)d_in[2];
    const float* u   = (const float*)d_in[3];
    const float* v   = (const float*)d_in[4];
    const float* z   = (const float*)d_in[5];
    float* out = (float*)d_out;
    (void)in_sizes; (void)n_in; (void)out_size;

    void* acc_ptr = nullptr;
    cudaGetSymbolAddress(&acc_ptr, g_acc);
    cudaMemsetAsync(acc_ptr, 0, 5 * B_DIM * sizeof(float));

    dim3 rgrid(B_DIM / (RED_THREADS * 4), N_DIM / ROWS);   // (2, 256)
    reduce_kernel<<<rgrid, RED_THREADS>>>(h, v, z);

    int fin_blocks = 2 * (N_DIM / NR);                      // 256
    finalize_kernel<<<fin_blocks, FIN_THREADS>>>(x_t, u, m, out);
}